// round 1
// baseline (speedup 1.0000x reference)
#include <cuda_runtime.h>
#include <math.h>

#define BATCH 256
#define NODE  256
#define DIM   64
#define TOPK  20
#define BNROWS 65536
#define XLS 66   // padded shared stride for xl rows

// ---------------- scratch (device globals; no allocations) ----------------
__device__ int   g_topk[NODE*TOPK];
__device__ float g_xl [BNROWS*DIM];
__device__ float g_agg[BNROWS*DIM];
__device__ float g_gnn[BNROWS*DIM];
__device__ float g_part1[64*DIM*2];
__device__ float g_part2[64*DIM*2];
__device__ float g_mean1[DIM], g_rstd1[DIM];
__device__ float g_mean2[DIM], g_rstd2[DIM];
__device__ float g_encP[64*BATCH*DIM];   // [kchunk][b][c]

__device__ __forceinline__ float lrelu(float x){ return x >= 0.f ? x : 0.2f*x; }

// ---------------- K1: cosine topk (graph structure) ----------------
__global__ void k_topk(const float* __restrict__ emb){
    __shared__ float nrm[NODE];
    __shared__ float vals[NODE];
    __shared__ float redV[NODE];
    __shared__ int   redI[NODE];
    int i = blockIdx.x;
    int j = threadIdx.x;
    const float* wj = emb + j*DIM;
    float s = 0.f;
#pragma unroll
    for (int k=0;k<DIM;k++){ float v = wj[k]; s += v*v; }
    nrm[j] = sqrtf(s);
    __syncthreads();
    const float* wi = emb + i*DIM;
    float d = 0.f;
#pragma unroll
    for (int k=0;k<DIM;k++) d += wi[k]*wj[k];
    vals[j] = d / (nrm[i]*nrm[j]);
    __syncthreads();
    // 20 rounds of stable argmax (ties -> lower index, matching jax top_k)
    for (int t=0;t<TOPK;t++){
        redV[j] = vals[j]; redI[j] = j;
        __syncthreads();
        for (int off=128; off>0; off>>=1){
            if (j < off){
                float v2 = redV[j+off]; int i2 = redI[j+off];
                if (v2 > redV[j] || (v2 == redV[j] && i2 < redI[j])){ redV[j]=v2; redI[j]=i2; }
            }
            __syncthreads();
        }
        if (j == 0) g_topk[i*TOPK + t] = redI[0];
        __syncthreads();
        if (j == redI[0]) vals[j] = -1e30f;
        __syncthreads();
    }
}

// ---------------- K2: xl = data @ lin_w  (64 rows / block) ----------------
__global__ void k_lin(const float* __restrict__ x, const float* __restrict__ lw){
    __shared__ float xs[64][65];
    __shared__ float ws[64][65];
    int r0 = blockIdx.x*64;
    int tid = threadIdx.x;
#pragma unroll
    for (int it=0; it<16; it++){
        int idx = tid + it*256;
        int r = idx>>6, c = idx&63;
        xs[r][c] = x[(r0+r)*64 + c];
        ws[r][c] = lw[idx];
    }
    __syncthreads();
    int tr = tid>>4, tc = tid&15;
    float acc[4][4] = {};
#pragma unroll 8
    for (int k=0;k<64;k++){
        float a[4], b[4];
#pragma unroll
        for (int u=0;u<4;u++){ a[u]=xs[tr*4+u][k]; b[u]=ws[k][tc*4+u]; }
#pragma unroll
        for (int u=0;u<4;u++)
#pragma unroll
            for (int v=0;v<4;v++) acc[u][v] += a[u]*b[v];
    }
#pragma unroll
    for (int u=0;u<4;u++)
#pragma unroll
        for (int v=0;v<4;v++)
            g_xl[(r0+tr*4+u)*64 + tc*4+v] = acc[u][v];
}

// ---------------- K3: per-batch GAT aggregation ----------------
// one block per batch; xl[b] staged in shared; softmax over 21 edges/node
__global__ void k_agg(const float* __restrict__ emb,
                      const float* __restrict__ att_i, const float* __restrict__ att_j,
                      const float* __restrict__ att_em_i, const float* __restrict__ att_em_j,
                      const float* __restrict__ gnn_bias){
    extern __shared__ float sm[];
    float* xls  = sm;                     // 256*66
    float* si   = xls + NODE*XLS;         // 256
    float* sj   = si + NODE;              // 256
    float* alp  = sj + NODE;              // 256*21
    float* attv = alp + NODE*21;          // 256  [att_i|att_j|att_em_i|att_em_j]
    int*   tk   = (int*)(attv + 256);     // 256*20

    int b = blockIdx.x;
    int tid = threadIdx.x;
    const float* xlb = g_xl + (size_t)b*NODE*DIM;
#pragma unroll
    for (int it=0; it<64; it++){
        int idx = tid + it*256;           // 0..16383
        xls[(idx>>6)*XLS + (idx&63)] = xlb[idx];
    }
    for (int idx=tid; idx<NODE*TOPK; idx+=256) tk[idx] = g_topk[idx];
    if (tid < 64)       attv[tid]       = att_i[tid];
    else if (tid < 128) attv[tid]       = att_j[tid-64];
    else if (tid < 192) attv[tid]       = att_em_i[tid-128];
    else                attv[tid]       = att_em_j[tid-192];
    __syncthreads();

    // per-node attention scalars
    {
        int i = tid;
        float ai = 0.f, aj = 0.f;
#pragma unroll
        for (int d=0; d<DIM; d++){
            float x = xls[i*XLS + d];
            float e = emb[i*DIM + d];
            ai += x*attv[d]    + e*attv[128+d];
            aj += x*attv[64+d] + e*attv[192+d];
        }
        si[i] = ai; sj[i] = aj;
    }
    __syncthreads();

    // softmax weights (thread i = node i); self loop at slot 20
    {
        int i = tid;
        float svi = si[i];
        float lself = lrelu(svi + sj[i]);
        float m = lself;
#pragma unroll 1
        for (int k=0;k<TOPK;k++){
            int s = tk[i*TOPK+k];
            if (s != i) m = fmaxf(m, lrelu(svi + sj[s]));
        }
        float sum = 0.f;
#pragma unroll 1
        for (int k=0;k<TOPK;k++){
            int s = tk[i*TOPK+k];
            float a = (s != i) ? expf(lrelu(svi + sj[s]) - m) : 0.f;
            alp[i*21+k] = a; sum += a;
        }
        float as = expf(lself - m);
        alp[i*21+20] = as; sum += as;
        float inv = 1.f/sum;
#pragma unroll
        for (int k=0;k<21;k++) alp[i*21+k] *= inv;
    }
    __syncthreads();

    // weighted aggregation: warp per node-group, lanes = channel pairs
    {
        int w = tid>>5, l = tid&31;
        for (int ii=0; ii<32; ii++){
            int i = w*32 + ii;
            float ax = 0.f, ay = 0.f;
            int base = i*21;
#pragma unroll 1
            for (int k=0;k<21;k++){
                float a = alp[base+k];
                int s = (k<TOPK) ? tk[i*TOPK+k] : i;
                float2 v = *(const float2*)&xls[s*XLS + 2*l];
                ax += a*v.x; ay += a*v.y;
            }
            int g = b*NODE + i;
            float2 o;
            o.x = ax + gnn_bias[2*l];
            o.y = ay + gnn_bias[2*l+1];
            *(float2*)&g_agg[(size_t)g*DIM + 2*l] = o;
        }
    }
}

// ---------------- K4: BN1 partial stats (deterministic) ----------------
__global__ void k_stat1(){
    int blk = blockIdx.x, tid = threadIdx.x;
    int c = tid&63, rg = tid>>6;
    size_t base = (size_t)blk*1024;
    float s=0.f, s2=0.f;
    for (int r=rg; r<1024; r+=4){
        float v = g_agg[(base+r)*DIM + c];
        s += v; s2 += v*v;
    }
    __shared__ float sh[2][256];
    sh[0][tid]=s; sh[1][tid]=s2;
    __syncthreads();
    if (tid < 64){
        float a=sh[0][tid], a2=sh[1][tid];
#pragma unroll
        for (int r=1;r<4;r++){ a+=sh[0][tid+r*64]; a2+=sh[1][tid+r*64]; }
        g_part1[(blk*64+tid)*2]   = a;
        g_part1[(blk*64+tid)*2+1] = a2;
    }
}

// ---------------- K5/K7: finalize BN stats ----------------
__global__ void k_fin(int which){
    const float* part = which ? g_part2 : g_part1;
    float* mean = which ? g_mean2 : g_mean1;
    float* rstd = which ? g_rstd2 : g_rstd1;
    int c = threadIdx.x;
    double s=0.0, s2=0.0;
    for (int k=0;k<64;k++){ s += part[(k*64+c)*2]; s2 += part[(k*64+c)*2+1]; }
    double m = s/65536.0;
    double var = s2/65536.0 - m*m;
    mean[c] = (float)m;
    rstd[c] = 1.0f/sqrtf((float)var + 1e-5f);
}

// ---------------- K6: gnn_out = relu(BN1(agg)); BN2 partial stats of y=gnn*emb ----------------
__global__ void k_gnn(const float* __restrict__ emb,
                      const float* __restrict__ g1, const float* __restrict__ b1){
    int blk = blockIdx.x, tid = threadIdx.x;
    int c = tid&63, rg = tid>>6;
    float mn = g_mean1[c], rs = g_rstd1[c], ga = g1[c], be = b1[c];
    size_t base = (size_t)blk*1024;
    float s=0.f, s2=0.f;
    for (int r=rg; r<1024; r+=4){
        size_t g = base + r;
        float v = g_agg[g*DIM + c];
        float gn = fmaxf(0.f, (v-mn)*rs*ga + be);
        g_gnn[g*DIM + c] = gn;
        int n = (int)(g & 255);
        float y = gn * emb[n*DIM + c];
        s += y; s2 += y*y;
    }
    __shared__ float sh[2][256];
    sh[0][tid]=s; sh[1][tid]=s2;
    __syncthreads();
    if (tid < 64){
        float a=sh[0][tid], a2=sh[1][tid];
#pragma unroll
        for (int r=1;r<4;r++){ a+=sh[0][tid+r*64]; a2+=sh[1][tid+r*64]; }
        g_part2[(blk*64+tid)*2]   = a;
        g_part2[(blk*64+tid)*2+1] = a2;
    }
}

// ---------------- K8: encoder GEMM partials, split-K(64) ----------------
__global__ void k_enc(const float* __restrict__ enc_w){
    __shared__ float As[64][65];
    __shared__ float Ws[64][65];
    int bt = blockIdx.x, kc = blockIdx.y;
    int tid = threadIdx.x;
    int tr = tid>>4, tc = tid&15;
    float acc[4][4] = {};
    for (int ks=0; ks<4; ks++){
        int kbase = kc*256 + ks*64;
        __syncthreads();
#pragma unroll
        for (int it=0; it<16; it++){
            int idx = tid + it*256;
            int r = idx>>6, c = idx&63;
            As[r][c] = g_gnn[(size_t)(bt*64+r)*16384 + kbase + c];
            Ws[r][c] = enc_w[(size_t)(kbase+r)*64 + c];
        }
        __syncthreads();
#pragma unroll 8
        for (int k=0;k<64;k++){
            float a[4], w[4];
#pragma unroll
            for (int u=0;u<4;u++){ a[u]=As[tr*4+u][k]; w[u]=Ws[k][tc*4+u]; }
#pragma unroll
            for (int u=0;u<4;u++)
#pragma unroll
                for (int v=0;v<4;v++) acc[u][v] += a[u]*w[v];
        }
    }
#pragma unroll
    for (int u=0;u<4;u++)
#pragma unroll
        for (int v=0;v<4;v++)
            g_encP[(size_t)(kc*256 + bt*64 + tr*4+u)*64 + (tc*4+v)] = acc[u][v];
}

// ---------------- K9: reduce encoder partials + arrangement head ----------------
__global__ void k_encfin(const float* __restrict__ enc_b, const float* __restrict__ arr_w,
                         const float* __restrict__ arr_b, float* __restrict__ out){
    int b = blockIdx.x, c = threadIdx.x;
    float s = 0.f;
    for (int kc=0;kc<64;kc++) s += g_encP[(size_t)(kc*256+b)*64 + c];
    s += enc_b[c];
    __shared__ float es[64];
    es[c] = s;
    __syncthreads();
    if (c < 7){
        float a = arr_b[c];
#pragma unroll
        for (int d=0; d<64; d++) a += es[d]*arr_w[d*7 + c];
        out[65536 + b*7 + c] = a;
    }
}

// ---------------- K10: score head (BN2 + relu + out_w dot) ----------------
__global__ void k_score(const float* __restrict__ emb,
                        const float* __restrict__ g2, const float* __restrict__ b2,
                        const float* __restrict__ out_w, const float* __restrict__ out_b,
                        float* __restrict__ out){
    int w = threadIdx.x>>5, l = threadIdx.x&31;
    int g = blockIdx.x*8 + w;
    int n = g & 255;
    int d = 2*l;
    float2 v = *(const float2*)&g_gnn[(size_t)g*DIM + d];
    float2 e = *(const float2*)&emb[n*DIM + d];
    float y0 = v.x*e.x, y1 = v.y*e.y;
    float r0 = fmaxf(0.f, (y0 - g_mean2[d  ])*g_rstd2[d  ]*g2[d  ] + b2[d  ]);
    float r1 = fmaxf(0.f, (y1 - g_mean2[d+1])*g_rstd2[d+1]*g2[d+1] + b2[d+1]);
    float p = r0*out_w[d] + r1*out_w[d+1];
#pragma unroll
    for (int off=16; off; off>>=1) p += __shfl_down_sync(0xffffffffu, p, off);
    if (l == 0) out[g] = p + out_b[0];
}

// ---------------- launcher ----------------
extern "C" void kernel_launch(void* const* d_in, const int* in_sizes, int n_in,
                              void* d_out, int out_size){
    const float* data     = (const float*)d_in[0];
    const float* emb      = (const float*)d_in[1];
    const float* lin_w    = (const float*)d_in[2];
    const float* att_i    = (const float*)d_in[3];
    const float* att_j    = (const float*)d_in[4];
    const float* att_em_i = (const float*)d_in[5];
    const float* att_em_j = (const float*)d_in[6];
    const float* gnn_bias = (const float*)d_in[7];
    const float* bn1_g    = (const float*)d_in[8];
    const float* bn1_b    = (const float*)d_in[9];
    const float* bn2_g    = (const float*)d_in[10];
    const float* bn2_b    = (const float*)d_in[11];
    const float* enc_w    = (const float*)d_in[12];
    const float* enc_b    = (const float*)d_in[13];
    const float* arr_w    = (const float*)d_in[14];
    const float* arr_b    = (const float*)d_in[15];
    const float* out_w    = (const float*)d_in[16];
    const float* out_b    = (const float*)d_in[17];
    float* out = (float*)d_out;

    const size_t aggSmem = (size_t)(NODE*XLS + 2*NODE + NODE*21 + 256)*4 + (size_t)NODE*TOPK*4;
    cudaFuncSetAttribute(k_agg, cudaFuncAttributeMaxDynamicSharedMemorySize, (int)aggSmem);

    k_topk<<<256,256>>>(emb);
    k_lin<<<1024,256>>>(data, lin_w);
    k_agg<<<256,256,aggSmem>>>(emb, att_i, att_j, att_em_i, att_em_j, gnn_bias);
    k_stat1<<<64,256>>>();
    k_fin<<<1,64>>>(0);
    k_gnn<<<64,256>>>(emb, bn1_g, bn1_b);
    k_fin<<<1,64>>>(1);
    k_enc<<<dim3(4,64),256>>>(enc_w);
    k_encfin<<<256,64>>>(enc_b, arr_w, arr_b, out);
    k_score<<<8192,256>>>(emb, bn2_g, bn2_b, out_w, out_b, out);
}

// round 3
// speedup vs baseline: 1.0710x; 1.0710x over previous
#include <cuda_runtime.h>
#include <math.h>

#define BATCH 256
#define NODE  256
#define DIM   64
#define TOPK  20
#define BNROWS 65536
#define XLS 66   // padded shared stride for xl rows

// ---------------- scratch (device globals; no allocations) ----------------
__device__ int   g_topk[NODE*TOPK];
__device__ float g_agg[BNROWS*DIM];
__device__ float g_part1[256*DIM*2];
__device__ float g_part2[256*DIM*2];
__device__ float g_mean1[DIM], g_rstd1[DIM];
__device__ float g_mean2[DIM], g_rstd2[DIM];
__device__ float g_encP[64*BATCH*DIM];   // [kchunk][b][c]

__device__ __forceinline__ float lrelu(float x){ return x >= 0.f ? x : 0.2f*x; }

// ---------------- K1: cosine topk (graph structure) ----------------
__global__ void k_topk(const float* __restrict__ emb){
    __shared__ float nrm[NODE];
    __shared__ float vals[NODE];
    __shared__ float wv[8];
    __shared__ int   wi[8];
    __shared__ int   winner;
    int i = blockIdx.x;
    int j = threadIdx.x;
    int lane = j & 31, warp = j >> 5;
    const float* wj = emb + j*DIM;
    float s = 0.f;
#pragma unroll
    for (int k=0;k<DIM;k++){ float v = wj[k]; s += v*v; }
    nrm[j] = sqrtf(s);
    __syncthreads();
    const float* wi_row = emb + i*DIM;
    float d = 0.f;
#pragma unroll
    for (int k=0;k<DIM;k++) d += wi_row[k]*wj[k];
    vals[j] = d / (nrm[i]*nrm[j]);
    __syncthreads();
    for (int t=0;t<TOPK;t++){
        float v = vals[j]; int idx = j;
#pragma unroll
        for (int off=16; off; off>>=1){
            float v2 = __shfl_xor_sync(0xffffffffu, v, off);
            int   i2 = __shfl_xor_sync(0xffffffffu, idx, off);
            if (v2 > v || (v2 == v && i2 < idx)){ v = v2; idx = i2; }
        }
        if (lane == 0){ wv[warp] = v; wi[warp] = idx; }
        __syncthreads();
        if (j < 8){
            float v8 = wv[j]; int i8 = wi[j];
#pragma unroll
            for (int off=4; off; off>>=1){
                float v2 = __shfl_xor_sync(0xffu, v8, off);
                int   i2 = __shfl_xor_sync(0xffu, i8, off);
                if (v2 > v8 || (v2 == v8 && i2 < i8)){ v8 = v2; i8 = i2; }
            }
            if (j == 0){ g_topk[i*TOPK + t] = i8; winner = i8; }
        }
        __syncthreads();
        if (j == winner) vals[j] = -3e38f;
        __syncthreads();
    }
}

// ---------------- K2: per-batch fused xl-GEMM + GAT aggregation + BN1 partial stats ----------------
// dynamic smem layout (floats):
//   xls[256*66] | si[256] | sj[256] | attv[256] | U[10496]
//   U phase A: ds[64*65] + lw[64*65] (GEMM tiles)
//   U phase B: tk[256*20 ints] + alp[256*21]
//   U phase C: sred[512 float4] (stats reduce)
__global__ __launch_bounds__(512,2) void k_agg(
        const float* __restrict__ data, const float* __restrict__ lin_w,
        const float* __restrict__ emb,
        const float* __restrict__ att_i, const float* __restrict__ att_j,
        const float* __restrict__ att_em_i, const float* __restrict__ att_em_j){
    extern __shared__ float sm[];
    float* xls  = sm;                     // 16896
    float* si   = xls + NODE*XLS;         // 256
    float* sj   = si + NODE;              // 256
    float* attv = sj + NODE;              // 256
    float* U    = attv + 256;             // 10496 floats union

    int b = blockIdx.x;
    int tid = threadIdx.x;

    // ---- phase A: xl = data[b] @ lin_w into xls ----
    float* ds = U;             // 64x65
    float* lw = U + 4160;      // 64x65
    // load lin_w + attv once
#pragma unroll
    for (int it=0; it<8; it++){
        int idx = tid + it*512;
        if (idx < 4096) lw[(idx>>6)*65 + (idx&63)] = lin_w[idx];
    }
    if (tid < 64)       attv[tid] = att_i[tid];
    else if (tid < 128) attv[tid] = att_j[tid-64];
    else if (tid < 192) attv[tid] = att_em_i[tid-128];
    else if (tid < 256) attv[tid] = att_em_j[tid-192];

    int tr = tid >> 4;     // 0..31  -> rows tr*2+u
    int tc = tid & 15;     // 0..15  -> cols tc*4+v
    const float* datb = data + (size_t)b*NODE*DIM;
    for (int ch=0; ch<4; ch++){
        int r0 = ch*64;
        __syncthreads();
#pragma unroll
        for (int it=0; it<8; it++){
            int idx = tid + it*512;
            ds[(idx>>6)*65 + (idx&63)] = datb[r0*64 + idx];
        }
        __syncthreads();
        float acc[2][4] = {};
#pragma unroll 8
        for (int k=0;k<64;k++){
            float a0 = ds[(tr*2+0)*65 + k];
            float a1 = ds[(tr*2+1)*65 + k];
            float w0 = lw[k*65 + tc*4+0];
            float w1 = lw[k*65 + tc*4+1];
            float w2 = lw[k*65 + tc*4+2];
            float w3 = lw[k*65 + tc*4+3];
            acc[0][0]+=a0*w0; acc[0][1]+=a0*w1; acc[0][2]+=a0*w2; acc[0][3]+=a0*w3;
            acc[1][0]+=a1*w0; acc[1][1]+=a1*w1; acc[1][2]+=a1*w2; acc[1][3]+=a1*w3;
        }
#pragma unroll
        for (int u=0;u<2;u++)
#pragma unroll
            for (int v=0;v<4;v++)
                xls[(r0+tr*2+u)*XLS + tc*4+v] = acc[u][v];
    }
    __syncthreads();

    // ---- phase B: load topk, per-node scalars, softmax ----
    int*   tk  = (int*)U;          // 5120 ints
    float* alp = U + 5120;         // 5376 floats
    for (int idx=tid; idx<NODE*TOPK; idx+=512) tk[idx] = g_topk[idx];
    if (tid < 256){
        int i = tid;
        float ai = 0.f, aj = 0.f;
#pragma unroll
        for (int d=0; d<DIM; d++){
            float x = xls[i*XLS + d];
            float e = emb[i*DIM + d];
            ai += x*attv[d]    + e*attv[128+d];
            aj += x*attv[64+d] + e*attv[192+d];
        }
        si[i] = ai; sj[i] = aj;
    }
    __syncthreads();
    if (tid < 256){
        int i = tid;
        float svi = si[i];
        float lself = lrelu(svi + sj[i]);
        float m = lself;
#pragma unroll 1
        for (int k=0;k<TOPK;k++){
            int s = tk[i*TOPK+k];
            if (s != i) m = fmaxf(m, lrelu(svi + sj[s]));
        }
        float sum = 0.f;
#pragma unroll 1
        for (int k=0;k<TOPK;k++){
            int s = tk[i*TOPK+k];
            float a = (s != i) ? expf(lrelu(svi + sj[s]) - m) : 0.f;
            alp[i*21+k] = a; sum += a;
        }
        float as = expf(lself - m);
        alp[i*21+20] = as; sum += as;
        float inv = 1.f/sum;
#pragma unroll
        for (int k=0;k<21;k++) alp[i*21+k] *= inv;
    }
    __syncthreads();

    // ---- phase C: weighted aggregation (16 warps x 16 nodes) + stats accumulate ----
    int w = tid>>5, l = tid&31;
    float s0=0.f, s20=0.f, s1=0.f, s21=0.f;
    for (int ii=0; ii<16; ii++){
        int i = w*16 + ii;
        float ax = 0.f, ay = 0.f;
        int base = i*21;
#pragma unroll 1
        for (int k=0;k<21;k++){
            float a = alp[base+k];
            int s = (k<TOPK) ? tk[i*TOPK+k] : i;
            float2 v = *(const float2*)&xls[s*XLS + 2*l];
            ax += a*v.x; ay += a*v.y;
        }
        int g = b*NODE + i;
        float2 o; o.x = ax; o.y = ay;
        *(float2*)&g_agg[(size_t)g*DIM + 2*l] = o;
        s0 += ax; s20 += ax*ax;
        s1 += ay; s21 += ay*ay;
    }
    __syncthreads();
    float4* sred = (float4*)U;
    sred[tid] = make_float4(s0, s20, s1, s21);
    __syncthreads();
    if (tid < 64){
        int c = tid, hl = c>>1, sel = c&1;
        float s=0.f, s2=0.f;
        for (int ww=0; ww<16; ww++){
            float4 v = sred[ww*32 + hl];
            s  += sel ? v.z : v.x;
            s2 += sel ? v.w : v.y;
        }
        g_part1[(b*64+c)*2]   = s;
        g_part1[(b*64+c)*2+1] = s2;
    }
}

// ---------------- K3: finalize BN stats (256 partials) ----------------
__global__ void k_fin(int which){
    const float* part = which ? g_part2 : g_part1;
    float* mean = which ? g_mean2 : g_mean1;
    float* rstd = which ? g_rstd2 : g_rstd1;
    int c = threadIdx.x;
    double s=0.0, s2=0.0;
    for (int p=0;p<256;p++){ s += part[(p*64+c)*2]; s2 += part[(p*64+c)*2+1]; }
    double m = s/65536.0;
    double var = s2/65536.0 - m*m;
    mean[c] = (float)m;
    rstd[c] = 1.0f/sqrtf((float)var + 1e-5f);
}

// ---------------- K4: encoder GEMM partials (split-K 64) with inline BN1+ReLU and BN2 partial stats ----------------
__global__ void k_enc(const float* __restrict__ enc_w, const float* __restrict__ emb,
                      const float* __restrict__ g1, const float* __restrict__ b1){
    __shared__ float As[64][65];
    __shared__ float Ws[64][65];
    __shared__ float sh[2][256];
    int bt = blockIdx.x, kc = blockIdx.y;
    int tid = threadIdx.x;
    int myc = tid & 63;
    float mn = g_mean1[myc], rs = g_rstd1[myc], ga = g1[myc], be = b1[myc];
    int tr = tid>>4, tc = tid&15;
    float acc[4][4] = {};
    float s = 0.f, s2 = 0.f;
    for (int ks=0; ks<4; ks++){
        int kbase = kc*256 + ks*64;
        int n = kc*4 + ks;                  // node index for this tile
        float embv = emb[n*64 + myc];
        __syncthreads();
#pragma unroll
        for (int it=0; it<16; it++){
            int idx = tid + it*256;
            int r = idx>>6, c = idx&63;
            float v = g_agg[(size_t)(bt*64+r)*16384 + kbase + c];
            float gn = fmaxf(0.f, (v - mn)*rs*ga + be);
            As[r][c] = gn;
            float y = gn * embv;
            s += y; s2 += y*y;
            Ws[r][c] = enc_w[(size_t)(kbase+r)*64 + c];
        }
        __syncthreads();
#pragma unroll 8
        for (int k=0;k<64;k++){
            float a[4], ww[4];
#pragma unroll
            for (int u=0;u<4;u++){ a[u]=As[tr*4+u][k]; ww[u]=Ws[k][tc*4+u]; }
#pragma unroll
            for (int u=0;u<4;u++)
#pragma unroll
                for (int v=0;v<4;v++) acc[u][v] += a[u]*ww[v];
        }
    }
#pragma unroll
    for (int u=0;u<4;u++)
#pragma unroll
        for (int v=0;v<4;v++)
            g_encP[(size_t)(kc*256 + bt*64 + tr*4+u)*64 + (tc*4+v)] = acc[u][v];
    __syncthreads();
    sh[0][tid]=s; sh[1][tid]=s2;
    __syncthreads();
    if (tid < 64){
        float a=sh[0][tid], a2=sh[1][tid];
#pragma unroll
        for (int r=1;r<4;r++){ a+=sh[0][tid+r*64]; a2+=sh[1][tid+r*64]; }
        int p = kc*4 + bt;
        g_part2[(p*64+tid)*2]   = a;
        g_part2[(p*64+tid)*2+1] = a2;
    }
}

// ---------------- K5: reduce encoder partials + arrangement head ----------------
__global__ void k_encfin(const float* __restrict__ enc_b, const float* __restrict__ arr_w,
                         const float* __restrict__ arr_b, float* __restrict__ out){
    int b = blockIdx.x, c = threadIdx.x;
    float s = 0.f;
    for (int kc=0;kc<64;kc++) s += g_encP[(size_t)(kc*256+b)*64 + c];
    s += enc_b[c];
    __shared__ float es[64];
    es[c] = s;
    __syncthreads();
    if (c < 7){
        float a = arr_b[c];
#pragma unroll
        for (int d=0; d<64; d++) a += es[d]*arr_w[d*7 + c];
        out[65536 + b*7 + c] = a;
    }
}

// ---------------- K6: score head (BN1 inline + mul emb + BN2 + relu + dot) ----------------
__global__ void k_score(const float* __restrict__ emb,
                        const float* __restrict__ g1, const float* __restrict__ b1,
                        const float* __restrict__ g2, const float* __restrict__ b2,
                        const float* __restrict__ out_w, const float* __restrict__ out_b,
                        float* __restrict__ out){
    int w = threadIdx.x>>5, l = threadIdx.x&31;
    int g = blockIdx.x*8 + w;
    int n = g & 255;
    int d = 2*l;
    float2 v = *(const float2*)&g_agg[(size_t)g*DIM + d];
    float2 e = *(const float2*)&emb[n*DIM + d];
    float gn0 = fmaxf(0.f, (v.x - g_mean1[d  ])*g_rstd1[d  ]*g1[d  ] + b1[d  ]);
    float gn1 = fmaxf(0.f, (v.y - g_mean1[d+1])*g_rstd1[d+1]*g1[d+1] + b1[d+1]);
    float y0 = gn0*e.x, y1 = gn1*e.y;
    float r0 = fmaxf(0.f, (y0 - g_mean2[d  ])*g_rstd2[d  ]*g2[d  ] + b2[d  ]);
    float r1 = fmaxf(0.f, (y1 - g_mean2[d+1])*g_rstd2[d+1]*g2[d+1] + b2[d+1]);
    float p = r0*out_w[d] + r1*out_w[d+1];
#pragma unroll
    for (int off=16; off; off>>=1) p += __shfl_down_sync(0xffffffffu, p, off);
    if (l == 0) out[g] = p + out_b[0];
}

// ---------------- launcher ----------------
extern "C" void kernel_launch(void* const* d_in, const int* in_sizes, int n_in,
                              void* d_out, int out_size){
    const float* data     = (const float*)d_in[0];
    const float* emb      = (const float*)d_in[1];
    const float* lin_w    = (const float*)d_in[2];
    const float* att_i    = (const float*)d_in[3];
    const float* att_j    = (const float*)d_in[4];
    const float* att_em_i = (const float*)d_in[5];
    const float* att_em_j = (const float*)d_in[6];
    // d_in[7] = gnn_bias: cancels exactly inside BN1 (per-channel constant)
    const float* bn1_g    = (const float*)d_in[8];
    const float* bn1_b    = (const float*)d_in[9];
    const float* bn2_g    = (const float*)d_in[10];
    const float* bn2_b    = (const float*)d_in[11];
    const float* enc_w    = (const float*)d_in[12];
    const float* enc_b    = (const float*)d_in[13];
    const float* arr_w    = (const float*)d_in[14];
    const float* arr_b    = (const float*)d_in[15];
    const float* out_w    = (const float*)d_in[16];
    const float* out_b    = (const float*)d_in[17];
    float* out = (float*)d_out;

    const size_t aggSmem = (size_t)(NODE*XLS + 3*256 + 10496)*4;   // 112640 B
    cudaFuncSetAttribute(k_agg, cudaFuncAttributeMaxDynamicSharedMemorySize, (int)aggSmem);

    k_topk<<<256,256>>>(emb);
    k_agg<<<256,512,aggSmem>>>(data, lin_w, emb, att_i, att_j, att_em_i, att_em_j);
    k_fin<<<1,64>>>(0);
    k_enc<<<dim3(4,64),256>>>(enc_w, emb, bn1_g, bn1_b);
    k_fin<<<1,64>>>(1);
    k_encfin<<<256,64>>>(enc_b, arr_w, arr_b, out);
    k_score<<<8192,256>>>(emb, bn1_g, bn1_b, bn2_g, bn2_b, out_w, out_b, out);
}

// round 9
// speedup vs baseline: 1.5359x; 1.4341x over previous
#include <cuda_runtime.h>
#include <math.h>

#define BATCH 256
#define NODE  256
#define DIM   64
#define TOPK  20
#define BNROWS 65536
#define XLS 66   // padded shared stride for xl rows

// ---------------- scratch (device globals; no allocations) ----------------
__device__ int   g_topk[NODE*TOPK];
__device__ float g_agg[BNROWS*DIM];
__device__ float g_part1[256*DIM*2];
__device__ float g_part2[512*DIM*2];
__device__ float g_mean1[DIM], g_rstd1[DIM];
__device__ float g_mean2[DIM], g_rstd2[DIM];
__device__ float g_W2[16384*7];          // enc_w @ arr_w
__device__ float g_arrP[16*BATCH*7];     // [kc][b][j] partials

__device__ __forceinline__ float lrelu(float x){ return x >= 0.f ? x : 0.2f*x; }

// ---------------- K1: cosine topk (graph structure) ----------------
__global__ void k_topk(const float* __restrict__ emb){
    __shared__ float nrm[NODE];
    __shared__ float vals[NODE];
    __shared__ float wv[8];
    __shared__ int   wi[8];
    __shared__ int   winner;
    int i = blockIdx.x;
    int j = threadIdx.x;
    int lane = j & 31, warp = j >> 5;
    const float* wj = emb + j*DIM;
    float s = 0.f;
#pragma unroll
    for (int k=0;k<DIM;k++){ float v = wj[k]; s += v*v; }
    nrm[j] = sqrtf(s);
    __syncthreads();
    const float* wi_row = emb + i*DIM;
    float d = 0.f;
#pragma unroll
    for (int k=0;k<DIM;k++) d += wi_row[k]*wj[k];
    vals[j] = d / (nrm[i]*nrm[j]);
    __syncthreads();
    for (int t=0;t<TOPK;t++){
        float v = vals[j]; int idx = j;
#pragma unroll
        for (int off=16; off; off>>=1){
            float v2 = __shfl_xor_sync(0xffffffffu, v, off);
            int   i2 = __shfl_xor_sync(0xffffffffu, idx, off);
            if (v2 > v || (v2 == v && i2 < idx)){ v = v2; idx = i2; }
        }
        if (lane == 0){ wv[warp] = v; wi[warp] = idx; }
        __syncthreads();
        if (j < 8){
            float v8 = wv[j]; int i8 = wi[j];
#pragma unroll
            for (int off=4; off; off>>=1){
                float v2 = __shfl_xor_sync(0xffu, v8, off);
                int   i2 = __shfl_xor_sync(0xffu, i8, off);
                if (v2 > v8 || (v2 == v8 && i2 < i8)){ v8 = v2; i8 = i2; }
            }
            if (j == 0){ g_topk[i*TOPK + t] = i8; winner = i8; }
        }
        __syncthreads();
        if (j == winner) vals[j] = -3e38f;
        __syncthreads();
    }
}

// ---------------- K2: precompute W2 = enc_w @ arr_w  [16384 x 7] ----------------
__global__ void k_prew(const float* __restrict__ enc_w, const float* __restrict__ arr_w){
    __shared__ float aws[64*7];
    int tid = threadIdx.x;
    for (int idx = tid; idx < 448; idx += 256) aws[idx] = arr_w[idx];   // FIX: strided (448 > blockDim)
    __syncthreads();
    int w = tid >> 5, l = tid & 31;
    for (int ii=0; ii<32; ii++){
        int k = blockIdx.x*256 + w*32 + ii;
        float2 e = *(const float2*)&enc_w[(size_t)k*64 + 2*l];
        float acc[7];
#pragma unroll
        for (int j=0;j<7;j++)
            acc[j] = e.x*aws[(2*l)*7+j] + e.y*aws[(2*l+1)*7+j];
#pragma unroll
        for (int j=0;j<7;j++){
#pragma unroll
            for (int off=16; off; off>>=1)
                acc[j] += __shfl_xor_sync(0xffffffffu, acc[j], off);
        }
        if (l == 0){
#pragma unroll
            for (int j=0;j<7;j++) g_W2[k*7+j] = acc[j];
        }
    }
}

// ---------------- K3: per-batch fused xl-GEMM + GAT aggregation + BN1 partial stats ----------------
__global__ __launch_bounds__(512,2) void k_agg(
        const float* __restrict__ data, const float* __restrict__ lin_w,
        const float* __restrict__ emb,
        const float* __restrict__ att_i, const float* __restrict__ att_j,
        const float* __restrict__ att_em_i, const float* __restrict__ att_em_j){
    extern __shared__ float sm[];
    float* xls  = sm;                     // 16896
    float* si   = xls + NODE*XLS;         // 256
    float* sj   = si + NODE;              // 256
    float* attv = sj + NODE;              // 256
    float* U    = attv + 256;             // 10496 floats union

    int b = blockIdx.x;
    int tid = threadIdx.x;

    // ---- phase A: xl = data[b] @ lin_w into xls ----
    float* ds = U;             // 64x65
    float* lw = U + 4160;      // 64x65
#pragma unroll
    for (int it=0; it<8; it++){
        int idx = tid + it*512;
        if (idx < 4096) lw[(idx>>6)*65 + (idx&63)] = lin_w[idx];
    }
    if (tid < 64)       attv[tid] = att_i[tid];
    else if (tid < 128) attv[tid] = att_j[tid-64];
    else if (tid < 192) attv[tid] = att_em_i[tid-128];
    else if (tid < 256) attv[tid] = att_em_j[tid-192];

    int tr = tid >> 4;     // 0..31
    int tc = tid & 15;     // 0..15
    const float* datb = data + (size_t)b*NODE*DIM;
    for (int ch=0; ch<4; ch++){
        int r0 = ch*64;
        __syncthreads();
#pragma unroll
        for (int it=0; it<8; it++){
            int idx = tid + it*512;
            ds[(idx>>6)*65 + (idx&63)] = datb[r0*64 + idx];
        }
        __syncthreads();
        float acc[2][4] = {};
#pragma unroll 8
        for (int k=0;k<64;k++){
            float a0 = ds[(tr*2+0)*65 + k];
            float a1 = ds[(tr*2+1)*65 + k];
            float w0 = lw[k*65 + tc*4+0];
            float w1 = lw[k*65 + tc*4+1];
            float w2 = lw[k*65 + tc*4+2];
            float w3 = lw[k*65 + tc*4+3];
            acc[0][0]+=a0*w0; acc[0][1]+=a0*w1; acc[0][2]+=a0*w2; acc[0][3]+=a0*w3;
            acc[1][0]+=a1*w0; acc[1][1]+=a1*w1; acc[1][2]+=a1*w2; acc[1][3]+=a1*w3;
        }
#pragma unroll
        for (int u=0;u<2;u++)
#pragma unroll
            for (int v=0;v<4;v++)
                xls[(r0+tr*2+u)*XLS + tc*4+v] = acc[u][v];
    }
    __syncthreads();

    // ---- phase B: topk, per-node scalars, softmax (fully unrolled for MLP) ----
    int*   tk  = (int*)U;          // 5120 ints
    float* alp = U + 5120;         // 5376 floats
    for (int idx=tid; idx<NODE*TOPK; idx+=512) tk[idx] = g_topk[idx];
    if (tid < 256){
        int i = tid;
        float ai = 0.f, aj = 0.f;
#pragma unroll
        for (int d=0; d<DIM; d++){
            float x = xls[i*XLS + d];
            float e = emb[i*DIM + d];
            ai += x*attv[d]    + e*attv[128+d];
            aj += x*attv[64+d] + e*attv[192+d];
        }
        si[i] = ai; sj[i] = aj;
    }
    __syncthreads();
    if (tid < 256){
        int i = tid;
        float svi = si[i];
        int   sidx[TOPK];
        float lv[TOPK];
#pragma unroll
        for (int k=0;k<TOPK;k++) sidx[k] = tk[i*TOPK+k];
#pragma unroll
        for (int k=0;k<TOPK;k++) lv[k] = lrelu(svi + sj[sidx[k]]);
        float lself = lrelu(svi + sj[i]);
        float m = lself;
#pragma unroll
        for (int k=0;k<TOPK;k++) if (sidx[k] != i) m = fmaxf(m, lv[k]);
        float sum = 0.f;
#pragma unroll
        for (int k=0;k<TOPK;k++){
            float a = (sidx[k] != i) ? expf(lv[k] - m) : 0.f;
            alp[i*21+k] = a; sum += a;
        }
        float as = expf(lself - m);
        alp[i*21+20] = as; sum += as;
        float inv = 1.f/sum;
#pragma unroll
        for (int k=0;k<21;k++) alp[i*21+k] *= inv;
    }
    __syncthreads();

    // ---- phase C: weighted aggregation + stats accumulate ----
    int w = tid>>5, l = tid&31;
    float s0=0.f, s20=0.f, s1=0.f, s21=0.f;
#pragma unroll 2
    for (int ii=0; ii<16; ii++){
        int i = w*16 + ii;
        float ax = 0.f, ay = 0.f;
        int base = i*21;
#pragma unroll
        for (int k=0;k<21;k++){
            float a = alp[base+k];
            int s = (k<TOPK) ? tk[i*TOPK+k] : i;
            float2 v = *(const float2*)&xls[s*XLS + 2*l];
            ax += a*v.x; ay += a*v.y;
        }
        int g = b*NODE + i;
        float2 o; o.x = ax; o.y = ay;
        *(float2*)&g_agg[(size_t)g*DIM + 2*l] = o;
        s0 += ax; s20 += ax*ax;
        s1 += ay; s21 += ay*ay;
    }
    __syncthreads();
    float4* sred = (float4*)U;
    sred[tid] = make_float4(s0, s20, s1, s21);
    __syncthreads();
    if (tid < 64){
        int c = tid, hl = c>>1, sel = c&1;
        float s=0.f, s2=0.f;
        for (int ww=0; ww<16; ww++){
            float4 v = sred[ww*32 + hl];
            s  += sel ? v.z : v.x;
            s2 += sel ? v.w : v.y;
        }
        g_part1[(b*64+c)*2]   = s;
        g_part1[(b*64+c)*2+1] = s2;
    }
}

// ---------------- K4: finalize BN stats ----------------
__global__ void k_fin(int which){
    const float* part = which ? g_part2 : g_part1;
    float* mean = which ? g_mean2 : g_mean1;
    float* rstd = which ? g_rstd2 : g_rstd1;
    int nPart = which ? 512 : 256;
    __shared__ float sh[2][256];
    int tid = threadIdx.x;
    int c = tid & 63, q = tid >> 6;
    float s=0.f, s2=0.f;
    for (int p=q; p<nPart; p+=4){ s += part[(p*64+c)*2]; s2 += part[(p*64+c)*2+1]; }
    sh[0][tid]=s; sh[1][tid]=s2;
    __syncthreads();
    if (tid < 64){
        double ds=0.0, ds2=0.0;
#pragma unroll
        for (int r=0;r<4;r++){ ds+=(double)sh[0][tid+r*64]; ds2+=(double)sh[1][tid+r*64]; }
        double m = ds/65536.0;
        double var = ds2/65536.0 - m*m;
        mean[tid] = (float)m;
        rstd[tid] = 1.0f/sqrtf((float)var + 1e-5f);
    }
}

// ---------------- K5: arrangement partials via W2 + BN1 inline + BN2 partial stats ----------------
__global__ __launch_bounds__(256) void k_encarr(
        const float* __restrict__ emb,
        const float* __restrict__ g1, const float* __restrict__ b1){
    __shared__ float W2s[1024*7];
    __shared__ float mns[64], rss[64], gas[64], bes[64];
    __shared__ float4 sred[8][64];
    int tid = threadIdx.x;
    int kc = blockIdx.y;
    int kbase = kc*1024;
#pragma unroll
    for (int it=0; it<28; it++) W2s[tid + it*256] = g_W2[(size_t)kbase*7 + tid + it*256];
    if (tid < 64){
        float mv = g_mean1[tid], rv = g_rstd1[tid];
        mns[tid] = mv; rss[tid] = rv; gas[tid] = g1[tid]; bes[tid] = b1[tid];
    }
    __syncthreads();

    int w = tid>>5, l = tid&31;
    int b = blockIdx.x*8 + w;
    float mn0 = mns[l],    rs0 = rss[l],    ga0 = gas[l],    be0 = bes[l];
    float mn1 = mns[l+32], rs1 = rss[l+32], ga1 = gas[l+32], be1 = bes[l+32];

    const float* arow = g_agg + (size_t)b*16384 + kbase;
    float acc[7] = {};
    float s0=0.f, s20=0.f, s1=0.f, s21=0.f;
#pragma unroll 4
    for (int t=0; t<32; t++){
        int kl = t*32 + l;
        float v = arow[kl];
        int n = kc*16 + (t>>1);
        float gn, y;
        if ((t & 1) == 0){
            gn = fmaxf(0.f, (v - mn0)*rs0*ga0 + be0);
            y = gn * emb[n*64 + l];
            s0 += y; s20 += y*y;
        } else {
            gn = fmaxf(0.f, (v - mn1)*rs1*ga1 + be1);
            y = gn * emb[n*64 + l + 32];
            s1 += y; s21 += y*y;
        }
        int wb = kl*7;
#pragma unroll
        for (int j=0;j<7;j++) acc[j] += gn * W2s[wb + j];
    }
#pragma unroll
    for (int j=0;j<7;j++){
#pragma unroll
        for (int off=16; off; off>>=1)
            acc[j] += __shfl_xor_sync(0xffffffffu, acc[j], off);
    }
    if (l == 0){
#pragma unroll
        for (int j=0;j<7;j++) g_arrP[(kc*256 + b)*7 + j] = acc[j];
    }
    sred[w][l]      = make_float4(s0, s20, 0.f, 0.f);
    sred[w][l+32]   = make_float4(s1, s21, 0.f, 0.f);
    __syncthreads();
    if (tid < 64){
        float s=0.f, s2=0.f;
#pragma unroll
        for (int ww=0; ww<8; ww++){
            float4 v = sred[ww][tid];
            s += v.x; s2 += v.y;
        }
        int pid = blockIdx.y*32 + blockIdx.x;
        g_part2[(pid*64+tid)*2]   = s;
        g_part2[(pid*64+tid)*2+1] = s2;
    }
}

// ---------------- K6: finalize arrangement (reduce partials + folded biases) ----------------
__global__ void k_arrfin(const float* __restrict__ enc_b, const float* __restrict__ arr_w,
                         const float* __restrict__ arr_b, float* __restrict__ out){
    int gid = blockIdx.x*256 + threadIdx.x;
    if (gid >= BATCH*7) return;
    int b = gid / 7, j = gid - b*7;
    float s = 0.f;
#pragma unroll
    for (int kc=0;kc<16;kc++) s += g_arrP[(kc*256 + b)*7 + j];
    float bias = arr_b[j];
#pragma unroll
    for (int c=0;c<64;c++) bias += enc_b[c]*arr_w[c*7+j];
    out[65536 + gid] = s + bias;
}

// ---------------- K7: score head (BN1 inline + mul emb + BN2 + relu + dot) ----------------
__global__ void k_score(const float* __restrict__ emb,
                        const float* __restrict__ g1, const float* __restrict__ b1,
                        const float* __restrict__ g2, const float* __restrict__ b2,
                        const float* __restrict__ out_w, const float* __restrict__ out_b,
                        float* __restrict__ out){
    int w = threadIdx.x>>5, l = threadIdx.x&31;
    int g = blockIdx.x*8 + w;
    int n = g & 255;
    int d = 2*l;
    float2 v = *(const float2*)&g_agg[(size_t)g*DIM + d];
    float2 e = *(const float2*)&emb[n*DIM + d];
    float gn0 = fmaxf(0.f, (v.x - g_mean1[d  ])*g_rstd1[d  ]*g1[d  ] + b1[d  ]);
    float gn1 = fmaxf(0.f, (v.y - g_mean1[d+1])*g_rstd1[d+1]*g1[d+1] + b1[d+1]);
    float y0 = gn0*e.x, y1 = gn1*e.y;
    float r0 = fmaxf(0.f, (y0 - g_mean2[d  ])*g_rstd2[d  ]*g2[d  ] + b2[d  ]);
    float r1 = fmaxf(0.f, (y1 - g_mean2[d+1])*g_rstd2[d+1]*g2[d+1] + b2[d+1]);
    float p = r0*out_w[d] + r1*out_w[d+1];
#pragma unroll
    for (int off=16; off; off>>=1) p += __shfl_down_sync(0xffffffffu, p, off);
    if (l == 0) out[g] = p + out_b[0];
}

// ---------------- launcher ----------------
extern "C" void kernel_launch(void* const* d_in, const int* in_sizes, int n_in,
                              void* d_out, int out_size){
    const float* data     = (const float*)d_in[0];
    const float* emb      = (const float*)d_in[1];
    const float* lin_w    = (const float*)d_in[2];
    const float* att_i    = (const float*)d_in[3];
    const float* att_j    = (const float*)d_in[4];
    const float* att_em_i = (const float*)d_in[5];
    const float* att_em_j = (const float*)d_in[6];
    // d_in[7] = gnn_bias: cancels exactly inside BN1 (per-channel constant)
    const float* bn1_g    = (const float*)d_in[8];
    const float* bn1_b    = (const float*)d_in[9];
    const float* bn2_g    = (const float*)d_in[10];
    const float* bn2_b    = (const float*)d_in[11];
    const float* enc_w    = (const float*)d_in[12];
    const float* enc_b    = (const float*)d_in[13];
    const float* arr_w    = (const float*)d_in[14];
    const float* arr_b    = (const float*)d_in[15];
    const float* out_w    = (const float*)d_in[16];
    const float* out_b    = (const float*)d_in[17];
    float* out = (float*)d_out;

    const size_t aggSmem = (size_t)(NODE*XLS + 3*256 + 10496)*4;   // 112640 B
    cudaFuncSetAttribute(k_agg, cudaFuncAttributeMaxDynamicSharedMemorySize, (int)aggSmem);

    k_topk<<<256,256>>>(emb);
    k_prew<<<64,256>>>(enc_w, arr_w);
    k_agg<<<256,512,aggSmem>>>(data, lin_w, emb, att_i, att_j, att_em_i, att_em_j);
    k_fin<<<1,256>>>(0);
    k_encarr<<<dim3(32,16),256>>>(emb, bn1_g, bn1_b);
    k_arrfin<<<7,256>>>(enc_b, arr_w, arr_b, out);
    k_fin<<<1,256>>>(1);
    k_score<<<8192,256>>>(emb, bn1_g, bn1_b, bn2_g, bn2_b, out_w, out_b, out);
}